// round 7
// baseline (speedup 1.0000x reference)
#include <cuda_runtime.h>

#define B_ 2
#define T_ 2048
#define H_ 16
#define DH_ 64
#define DIN_ 1024
#define DINNER_ 1024
#define DOUT_ 64
#define BT_ 4096

#define FULLM 0xffffffffu

__device__ float g_Q[B_*H_*T_*DH_];     // [b,h,t,d]  tf32-rounded
__device__ float g_K[B_*H_*T_*DH_];     // [b,h,t,perm8(d)] tf32-rounded
__device__ float g_V[B_*H_*T_*DH_];     // [b,h,d,perm8(t)] tf32-rounded (transposed)
__device__ float g_attn[BT_*DINNER_];   // [b*T+t, h*64+d]  tf32-rounded
__device__ float g_x32[BT_*DIN_];       // tf32-rounded x
__device__ float g_w32[3][DIN_*DINNER_];// tf32-rounded Wq,Wk,Wv
__device__ float g_wo32[DINNER_*DOUT_]; // tf32-rounded Wo

__device__ __forceinline__ unsigned f2tf(float x) {
    unsigned u; asm("cvt.rna.tf32.f32 %0, %1;" : "=r"(u) : "f"(x)); return u;
}
__device__ __forceinline__ float f2tff(float x) {
    return __uint_as_float(f2tf(x));
}
__device__ __forceinline__ void mma8(float c[4],
    unsigned a0, unsigned a1, unsigned a2, unsigned a3,
    unsigned b0, unsigned b1)
{
    asm volatile("mma.sync.aligned.m16n8k8.row.col.f32.tf32.tf32.f32 "
        "{%0,%1,%2,%3}, {%4,%5,%6,%7}, {%8,%9}, {%0,%1,%2,%3};"
        : "+f"(c[0]), "+f"(c[1]), "+f"(c[2]), "+f"(c[3])
        : "r"(a0), "r"(a1), "r"(a2), "r"(a3), "r"(b0), "r"(b1));
}
__device__ __forceinline__ int perm8(int i) {
    return (i & ~7) + 2 * (i & 3) + ((i >> 2) & 1);
}

// ---------------------------------------------------------------------------
// Kernel 0: round all GEMM inputs to tf32 (RNA) in ONE launch.
// ---------------------------------------------------------------------------
#define XF4  (BT_*DIN_/4)
#define WF4  (DIN_*DINNER_/4)
#define WOF4 (DINNER_*DOUT_/4)
#define TOTF4 (XF4 + 3*WF4 + WOF4)

__global__ __launch_bounds__(256) void tf32_round_all(
    const float4* __restrict__ x, const float4* __restrict__ wq,
    const float4* __restrict__ wk, const float4* __restrict__ wv,
    const float4* __restrict__ wo)
{
    int i = blockIdx.x * 256 + threadIdx.x;
    if (i >= TOTF4) return;
    const float4* src;
    float4* dst;
    if (i < XF4) {
        src = x + i; dst = (float4*)g_x32 + i;
    } else {
        int j = i - XF4;
        if (j < 3 * WF4) {
            int w = j >> 18;
            int o = j & (WF4 - 1);
            src = ((w == 0) ? wq : (w == 1) ? wk : wv) + o;
            dst = (float4*)&g_w32[w][0] + o;
        } else {
            int o = j - 3 * WF4;
            src = wo + o; dst = (float4*)g_wo32 + o;
        }
    }
    float4 v = *src;
    float4 r;
    r.x = f2tff(v.x); r.y = f2tff(v.y); r.z = f2tff(v.z); r.w = f2tff(v.w);
    *dst = r;
}

// ---------------------------------------------------------------------------
// Kernel 1: fused QKV projection, tf32 mma, cp.async TRIPLE-buffered.
// Epilogue: Q natural, K d-permuted, V transposed+t-permuted (all rounded).
// ---------------------------------------------------------------------------
#define AST 20
#define BST 136
#define ASTG (128*AST)
#define BSTG (16*BST)

__global__ __launch_bounds__(128) void qkv_mma_kernel()
{
    __shared__ float As[3 * ASTG];
    __shared__ float Bs[3 * BSTG];

    const int z = blockIdx.z;
    const float* __restrict__ X = g_x32;
    const float* __restrict__ W = &g_w32[z][0];

    const int m0 = blockIdx.y * 128, n0 = blockIdx.x * 128;
    const int tid = threadIdx.x, lane = tid & 31, warp = tid >> 5;
    const int g = lane >> 2, tq = lane & 3;
    const int wm = (warp >> 1) * 64, wn = (warp & 1) * 64;

    const unsigned sA = (unsigned)__cvta_generic_to_shared(As);
    const unsigned sB = (unsigned)__cvta_generic_to_shared(Bs);

    const int ar = tid >> 2, ac4 = tid & 3;
    const int bk = tid >> 5, bc4 = tid & 31;

#define ISSUE(CH, ST) do {                                                   \
    const float* ga_ = X + (size_t)(m0 + ar) * DIN_ + (CH) * 16 + ac4 * 4;   \
    unsigned da_ = sA + (unsigned)(((ST) * ASTG + ar * AST + ac4 * 4) * 4);  \
    _Pragma("unroll")                                                        \
    for (int u_ = 0; u_ < 4; u_++)                                           \
        asm volatile("cp.async.cg.shared.global [%0], [%1], 16;"             \
            :: "r"(da_ + u_ * 32 * AST * 4), "l"(ga_ + (size_t)32 * u_ * DIN_)); \
    const float* gb_ = W + (size_t)((CH) * 16 + bk) * DINNER_ + n0 + bc4 * 4;\
    unsigned db_ = sB + (unsigned)(((ST) * BSTG + bk * BST + bc4 * 4) * 4);  \
    _Pragma("unroll")                                                        \
    for (int u_ = 0; u_ < 4; u_++)                                           \
        asm volatile("cp.async.cg.shared.global [%0], [%1], 16;"             \
            :: "r"(db_ + u_ * 4 * BST * 4), "l"(gb_ + (size_t)4 * u_ * DINNER_)); \
    asm volatile("cp.async.commit_group;" ::: "memory");                     \
} while (0)

    float acc[4][8][4];
    #pragma unroll
    for (int i = 0; i < 4; i++)
        #pragma unroll
        for (int j = 0; j < 8; j++)
            #pragma unroll
            for (int r = 0; r < 4; r++) acc[i][j][r] = 0.f;

    const unsigned* Au = (const unsigned*)As;
    const unsigned* Bu = (const unsigned*)Bs;

    ISSUE(0, 0);
    ISSUE(1, 1);

    int st = 0;
    for (int ch = 0; ch < 64; ++ch) {
        if (ch < 62) {
            int s2 = (st >= 1) ? st - 1 : st + 2;   // (st+2) mod 3
            ISSUE(ch + 2, s2);
            asm volatile("cp.async.wait_group 2;" ::: "memory");
        } else if (ch == 62) {
            asm volatile("cp.async.wait_group 1;" ::: "memory");
        } else {
            asm volatile("cp.async.wait_group 0;" ::: "memory");
        }
        __syncthreads();

        const unsigned* A0 = Au + st * ASTG;
        const unsigned* B0 = Bu + st * BSTG;
        #pragma unroll
        for (int ks = 0; ks < 2; ++ks) {
            unsigned a0[4], a1[4], a2[4], a3[4];
            #pragma unroll
            for (int mf = 0; mf < 4; mf++) {
                int base = (wm + mf * 16 + g) * AST + ks * 8 + tq;
                a0[mf] = A0[base];
                a2[mf] = A0[base + 4];
                a1[mf] = A0[base + 8 * AST];
                a3[mf] = A0[base + 8 * AST + 4];
            }
            unsigned b0[8], b1[8];
            #pragma unroll
            for (int nf = 0; nf < 8; nf++) {
                int cidx = wn + nf * 8 + g;
                b0[nf] = B0[(ks * 8 + tq) * BST + cidx];
                b1[nf] = B0[(ks * 8 + tq + 4) * BST + cidx];
            }
            #pragma unroll
            for (int mf = 0; mf < 4; mf++)
                #pragma unroll
                for (int nf = 0; nf < 8; nf++)
                    mma8(acc[mf][nf], a0[mf], a1[mf], a2[mf], a3[mf], b0[nf], b1[nf]);
        }
        __syncthreads();
        st = (st == 2) ? 0 : st + 1;
    }

    // Epilogue
    #pragma unroll
    for (int mf = 0; mf < 4; mf++) {
        int row_a = m0 + wm + mf * 16 + g;
        int row_b = row_a + 8;
        int ba = row_a >> 11, ta = row_a & 2047;
        int bbq = row_b >> 11, tb = row_b & 2047;
        #pragma unroll
        for (int nf = 0; nf < 8; nf++) {
            int col = n0 + wn + nf * 8 + 2 * tq;
            int h = col >> 6, d = col & 63;
            float v0 = f2tff(acc[mf][nf][0]);
            float v1 = f2tff(acc[mf][nf][1]);
            float v2 = f2tff(acc[mf][nf][2]);
            float v3 = f2tff(acc[mf][nf][3]);
            if (z == 0) {
                *(float2*)(g_Q + ((size_t)((ba * H_ + h) * T_) + ta) * DH_ + d)
                    = make_float2(v0, v1);
                *(float2*)(g_Q + ((size_t)((bbq * H_ + h) * T_) + tb) * DH_ + d)
                    = make_float2(v2, v3);
            } else if (z == 1) {
                int pd = perm8(d);
                float* oa = g_K + ((size_t)((ba * H_ + h) * T_) + ta) * DH_;
                oa[pd] = v0; oa[pd + 2] = v1;
                float* ob = g_K + ((size_t)((bbq * H_ + h) * T_) + tb) * DH_;
                ob[pd] = v2; ob[pd + 2] = v3;
            } else {
                float* vt0 = g_V + ((size_t)((ba * H_ + h) * DH_) + d) * T_;
                float* vt1 = vt0 + T_;
                int pa = perm8(ta), pb = perm8(tb);
                vt0[pa] = v0; vt1[pa] = v1;
                vt0[pb] = v2; vt1[pb] = v3;
            }
        }
    }
#undef ISSUE
}

// ---------------------------------------------------------------------------
// Kernel 2: causal flash attention, tf32 mma, cp.async double-buffered K/V.
// 3 CTAs/SM target (launch_bounds). Fully-masked warps skip the last
// diagonal tile (bit-identical: exp underflows to exactly 0).
// P fed to mma as raw fp32 (HW truncation to tf32).
// ---------------------------------------------------------------------------
#define KST 72
#define VST 72
#define KSTG (64*KST)
#define VSTG (64*VST)
#define ATTN_SMEM ((2*KSTG + 2*VSTG)*4)   // 73728 bytes

__global__ __launch_bounds__(128, 3) void attn_mma_kernel()
{
    extern __shared__ float dsm[];
    float* Ksm = dsm;
    float* Vsm = dsm + 2 * KSTG;

    const int qt = 15 - blockIdx.x;       // heavy tiles first
    const int bh = blockIdx.y;
    const int tid = threadIdx.x, warp = tid >> 5, lane = tid & 31;
    const int g = lane >> 2, tq = lane & 3;
    const int q0w = qt * 128 + warp * 32;

    const float* __restrict__ Qp = g_Q + (size_t)bh * T_ * DH_;
    const float* __restrict__ Kp = g_K + (size_t)bh * T_ * DH_;
    const float* __restrict__ Vp = g_V + (size_t)bh * T_ * DH_;

    const unsigned sK = (unsigned)__cvta_generic_to_shared(Ksm);
    const unsigned sV = (unsigned)__cvta_generic_to_shared(Vsm);

#define KV_ISSUE(KT, ST) do {                                                \
    const float* gk_ = Kp + (size_t)(KT) * 4096;                             \
    const float* gv_ = Vp + (KT) * 64;                                       \
    _Pragma("unroll")                                                        \
    for (int u_ = 0; u_ < 8; u_++) {                                         \
        int f4_ = tid + 128 * u_;                                            \
        int row_ = f4_ >> 4, c4_ = f4_ & 15;                                 \
        unsigned dk_ = sK + (unsigned)(((ST) * KSTG + row_ * KST + c4_ * 4) * 4); \
        asm volatile("cp.async.cg.shared.global [%0], [%1], 16;"             \
            :: "r"(dk_), "l"(gk_ + f4_ * 4));                                \
        unsigned dv_ = sV + (unsigned)(((ST) * VSTG + row_ * VST + c4_ * 4) * 4); \
        asm volatile("cp.async.cg.shared.global [%0], [%1], 16;"             \
            :: "r"(dv_), "l"(gv_ + (size_t)row_ * T_ + c4_ * 4));            \
    }                                                                        \
    asm volatile("cp.async.commit_group;" ::: "memory");                     \
} while (0)

    unsigned qf[2][8][4];
    #pragma unroll
    for (int m = 0; m < 2; m++) {
        const unsigned* qa = (const unsigned*)(Qp + (size_t)(q0w + 16 * m + g) * DH_);
        const unsigned* qb = qa + 8 * DH_;
        #pragma unroll
        for (int ks = 0; ks < 8; ks++) {
            qf[m][ks][0] = qa[ks * 8 + tq];
            qf[m][ks][1] = qb[ks * 8 + tq];
            qf[m][ks][2] = qa[ks * 8 + tq + 4];
            qf[m][ks][3] = qb[ks * 8 + tq + 4];
        }
    }

    float of[2][8][4];
    #pragma unroll
    for (int m = 0; m < 2; m++)
        #pragma unroll
        for (int d = 0; d < 8; d++)
            #pragma unroll
            for (int r = 0; r < 4; r++) of[m][d][r] = 0.f;
    float ls[2][2] = {{0.f, 0.f}, {0.f, 0.f}};

    const int grp = lane & ~3;
    const int sl0 = grp + (tq >> 1), sl1 = sl0 + 2;
    const bool od = (tq & 1);

    const unsigned* Ku = (const unsigned*)Ksm;
    const unsigned* Vu = (const unsigned*)Vsm;

    const int ktmax = 2 * qt + 1;
    KV_ISSUE(0, 0);

    for (int kt = 0; kt <= ktmax; ++kt) {
        const int st = kt & 1;
        __syncthreads();
        if (kt < ktmax) {
            KV_ISSUE(kt + 1, st ^ 1);
            asm volatile("cp.async.wait_group 1;" ::: "memory");
        } else {
            asm volatile("cp.async.wait_group 0;" ::: "memory");
        }
        __syncthreads();

        // On the last (odd-diagonal) tile, warps 0/1 are fully masked:
        // every p underflows to exactly 0 -> skipping is bit-identical.
        if (kt == ktmax && warp < 2) continue;

        const unsigned* K0 = Ku + st * KSTG;
        const unsigned* V0 = Vu + st * VSTG;

        // ---- S = Q K^T ----
        float c[2][8][4];
        #pragma unroll
        for (int m = 0; m < 2; m++)
            #pragma unroll
            for (int nf = 0; nf < 8; nf++)
                #pragma unroll
                for (int r = 0; r < 4; r++) c[m][nf][r] = 0.f;

        #pragma unroll
        for (int ks = 0; ks < 8; ks++) {
            uint2 kb[8];
            #pragma unroll
            for (int nf = 0; nf < 8; nf++)
                kb[nf] = *(const uint2*)&K0[(nf * 8 + g) * KST + ks * 8 + 2 * tq];
            #pragma unroll
            for (int m = 0; m < 2; m++)
                #pragma unroll
                for (int nf = 0; nf < 8; nf++)
                    mma8(c[m][nf], qf[m][ks][0], qf[m][ks][1], qf[m][ks][2], qf[m][ks][3],
                         kb[nf].x, kb[nf].y);
        }

        // ---- causal mask ----
        if (kt >= 2 * qt) {
            const int base = kt * 64;
            #pragma unroll
            for (int m = 0; m < 2; m++) {
                int r0 = q0w + 16 * m + g, r1 = r0 + 8;
                #pragma unroll
                for (int nf = 0; nf < 8; nf++) {
                    int col = base + nf * 8 + 2 * tq;
                    if (col     > r0) c[m][nf][0] = -1e30f;
                    if (col + 1 > r0) c[m][nf][1] = -1e30f;
                    if (col     > r1) c[m][nf][2] = -1e30f;
                    if (col + 1 > r1) c[m][nf][3] = -1e30f;
                }
            }
        }

        // ---- p = exp(s/32) ----
        #pragma unroll
        for (int m = 0; m < 2; m++)
            #pragma unroll
            for (int nf = 0; nf < 8; nf++) {
                c[m][nf][0] = __expf(c[m][nf][0] * 0.03125f);
                c[m][nf][1] = __expf(c[m][nf][1] * 0.03125f);
                c[m][nf][2] = __expf(c[m][nf][2] * 0.03125f);
                c[m][nf][3] = __expf(c[m][nf][3] * 0.03125f);
                ls[m][0] += c[m][nf][0] + c[m][nf][1];
                ls[m][1] += c[m][nf][2] + c[m][nf][3];
            }

        // ---- O += P V : P as raw fp32 (HW truncates to tf32) ----
        #pragma unroll
        for (int kk = 0; kk < 8; kk++) {
            unsigned A[2][4];
            #pragma unroll
            for (int m = 0; m < 2; m++) {
                float e0 = __shfl_sync(FULLM, c[m][kk][0], sl0);
                float o0 = __shfl_sync(FULLM, c[m][kk][1], sl0);
                float e1 = __shfl_sync(FULLM, c[m][kk][0], sl1);
                float o1 = __shfl_sync(FULLM, c[m][kk][1], sl1);
                float e2 = __shfl_sync(FULLM, c[m][kk][2], sl0);
                float o2 = __shfl_sync(FULLM, c[m][kk][3], sl0);
                float e3 = __shfl_sync(FULLM, c[m][kk][2], sl1);
                float o3 = __shfl_sync(FULLM, c[m][kk][3], sl1);
                A[m][0] = __float_as_uint(od ? o0 : e0);
                A[m][2] = __float_as_uint(od ? o1 : e1);
                A[m][1] = __float_as_uint(od ? o2 : e2);
                A[m][3] = __float_as_uint(od ? o3 : e3);
            }
            #pragma unroll
            for (int df = 0; df < 8; df++) {
                uint2 vb = *(const uint2*)&V0[(df * 8 + g) * VST + kk * 8 + 2 * tq];
                mma8(of[0][df], A[0][0], A[0][1], A[0][2], A[0][3], vb.x, vb.y);
                mma8(of[1][df], A[1][0], A[1][1], A[1][2], A[1][3], vb.x, vb.y);
            }
        }
    }
#undef KV_ISSUE

    #pragma unroll
    for (int m = 0; m < 2; m++)
        #pragma unroll
        for (int r = 0; r < 2; r++) {
            ls[m][r] += __shfl_xor_sync(FULLM, ls[m][r], 1);
            ls[m][r] += __shfl_xor_sync(FULLM, ls[m][r], 2);
        }

    const int bb = bh >> 4, hh = bh & 15;
    #pragma unroll
    for (int m = 0; m < 2; m++) {
        float i0 = 1.f / ls[m][0], i1 = 1.f / ls[m][1];
        int rowa = q0w + 16 * m + g, rowb = rowa + 8;
        float* oa = g_attn + (size_t)(bb * T_ + rowa) * DINNER_ + hh * 64;
        float* ob = g_attn + (size_t)(bb * T_ + rowb) * DINNER_ + hh * 64;
        #pragma unroll
        for (int df = 0; df < 8; df++) {
            *(float2*)(oa + df * 8 + 2 * tq)
                = make_float2(f2tff(of[m][df][0] * i0), f2tff(of[m][df][1] * i0));
            *(float2*)(ob + df * 8 + 2 * tq)
                = make_float2(f2tff(of[m][df][2] * i1), f2tff(of[m][df][3] * i1));
        }
    }
}

// ---------------------------------------------------------------------------
// Kernel 3: out projection via tf32 mma, k-split across 4 warps.
// CTA: m-tile 16, 128 thr; warp w does K[w*256,(w+1)*256), partials reduced
// through smem. 256 CTAs fill the chip; operands LDG'd straight from L2.
// ---------------------------------------------------------------------------
__global__ __launch_bounds__(128) void out_mma_kernel(
    const float* __restrict__ bo, float* __restrict__ out)
{
    __shared__ float red[4][16 * 64];

    const int m0 = blockIdx.x * 16;
    const int tid = threadIdx.x, lane = tid & 31, warp = tid >> 5;
    const int g = lane >> 2, tq = lane & 3;

    const unsigned* Ap = (const unsigned*)(g_attn + (size_t)m0 * DINNER_ + warp * 256);
    const unsigned* Bp = (const unsigned*)(g_wo32 + (size_t)warp * 256 * DOUT_);

    float acc[8][4];
    #pragma unroll
    for (int j = 0; j < 8; j++)
        #pragma unroll
        for (int r = 0; r < 4; r++) acc[j][r] = 0.f;

    #pragma unroll 4
    for (int k8 = 0; k8 < 32; ++k8) {
        unsigned a0 = Ap[(size_t)g * DINNER_ + k8 * 8 + tq];
        unsigned a1 = Ap[(size_t)(g + 8) * DINNER_ + k8 * 8 + tq];
        unsigned a2 = Ap[(size_t)g * DINNER_ + k8 * 8 + tq + 4];
        unsigned a3 = Ap[(size_t)(g + 8) * DINNER_ + k8 * 8 + tq + 4];
        #pragma unroll
        for (int nf = 0; nf < 8; nf++) {
            unsigned b0 = Bp[(k8 * 8 + tq) * DOUT_ + nf * 8 + g];
            unsigned b1 = Bp[(k8 * 8 + tq + 4) * DOUT_ + nf * 8 + g];
            mma8(acc[nf], a0, a1, a2, a3, b0, b1);
        }
    }

    float* rw = red[warp];
    #pragma unroll
    for (int nf = 0; nf < 8; nf++) {
        *(float2*)&rw[g * 64 + nf * 8 + 2 * tq]       = make_float2(acc[nf][0], acc[nf][1]);
        *(float2*)&rw[(g + 8) * 64 + nf * 8 + 2 * tq] = make_float2(acc[nf][2], acc[nf][3]);
    }
    __syncthreads();

    #pragma unroll
    for (int i = tid; i < 1024; i += 128) {
        int r = i >> 6, cix = i & 63;
        float s = red[0][i] + red[1][i] + red[2][i] + red[3][i] + bo[cix];
        out[(size_t)(m0 + r) * DOUT_ + cix] = s;
    }
}

// ---------------------------------------------------------------------------
extern "C" void kernel_launch(void* const* d_in, const int* in_sizes, int n_in,
                              void* d_out, int out_size)
{
    const float* x  = (const float*)d_in[0];
    const float* Wq = (const float*)d_in[1];
    const float* Wk = (const float*)d_in[2];
    const float* Wv = (const float*)d_in[3];
    const float* Wo = (const float*)d_in[4];
    const float* bo = (const float*)d_in[5];
    float* out = (float*)d_out;
    (void)in_sizes; (void)n_in; (void)out_size;

    cudaFuncSetAttribute(attn_mma_kernel,
                         cudaFuncAttributeMaxDynamicSharedMemorySize, ATTN_SMEM);

    tf32_round_all<<<(TOTF4 + 255) / 256, 256>>>(
        (const float4*)x, (const float4*)Wq, (const float4*)Wk,
        (const float4*)Wv, (const float4*)Wo);

    qkv_mma_kernel<<<dim3(8, 32, 3), 128>>>();
    attn_mma_kernel<<<dim3(16, 32), 128, ATTN_SMEM>>>();
    out_mma_kernel<<<BT_ / 16, 128>>>(bo, out);
}

// round 8
// speedup vs baseline: 1.2725x; 1.2725x over previous
#include <cuda_runtime.h>

#define B_ 2
#define T_ 2048
#define H_ 16
#define DH_ 64
#define DIN_ 1024
#define DINNER_ 1024
#define DOUT_ 64
#define BT_ 4096

#define FULLM 0xffffffffu

__device__ float g_Q[B_*H_*T_*DH_];     // [b,h,t,d]  tf32-rounded
__device__ float g_K[B_*H_*T_*DH_];     // [b,h,t,perm8(d)] tf32-rounded
__device__ float g_V[B_*H_*T_*DH_];     // [b,h,d,perm8(t)] tf32-rounded (transposed)
__device__ float g_attn[BT_*DINNER_];   // [b*T+t, h*64+d]  tf32-rounded
__device__ float g_x32[BT_*DIN_];       // tf32-rounded x
__device__ float g_w32[3][DIN_*DINNER_];// tf32-rounded Wq,Wk,Wv
__device__ float g_wo32[DINNER_*DOUT_]; // tf32-rounded Wo

__device__ __forceinline__ unsigned f2tf(float x) {
    unsigned u; asm("cvt.rna.tf32.f32 %0, %1;" : "=r"(u) : "f"(x)); return u;
}
__device__ __forceinline__ float f2tff(float x) {
    return __uint_as_float(f2tf(x));
}
__device__ __forceinline__ void mma8(float c[4],
    unsigned a0, unsigned a1, unsigned a2, unsigned a3,
    unsigned b0, unsigned b1)
{
    asm volatile("mma.sync.aligned.m16n8k8.row.col.f32.tf32.tf32.f32 "
        "{%0,%1,%2,%3}, {%4,%5,%6,%7}, {%8,%9}, {%0,%1,%2,%3};"
        : "+f"(c[0]), "+f"(c[1]), "+f"(c[2]), "+f"(c[3])
        : "r"(a0), "r"(a1), "r"(a2), "r"(a3), "r"(b0), "r"(b1));
}
__device__ __forceinline__ int perm8(int i) {
    return (i & ~7) + 2 * (i & 3) + ((i >> 2) & 1);
}

// ---------------------------------------------------------------------------
// Kernel 0: round all GEMM inputs to tf32 (RNA) in ONE launch.
// ---------------------------------------------------------------------------
#define XF4  (BT_*DIN_/4)
#define WF4  (DIN_*DINNER_/4)
#define WOF4 (DINNER_*DOUT_/4)
#define TOTF4 (XF4 + 3*WF4 + WOF4)

__global__ __launch_bounds__(256) void tf32_round_all(
    const float4* __restrict__ x, const float4* __restrict__ wq,
    const float4* __restrict__ wk, const float4* __restrict__ wv,
    const float4* __restrict__ wo)
{
    int i = blockIdx.x * 256 + threadIdx.x;
    if (i >= TOTF4) return;
    const float4* src;
    float4* dst;
    if (i < XF4) {
        src = x + i; dst = (float4*)g_x32 + i;
    } else {
        int j = i - XF4;
        if (j < 3 * WF4) {
            int w = j >> 18;
            int o = j & (WF4 - 1);
            src = ((w == 0) ? wq : (w == 1) ? wk : wv) + o;
            dst = (float4*)&g_w32[w][0] + o;
        } else {
            int o = j - 3 * WF4;
            src = wo + o; dst = (float4*)g_wo32 + o;
        }
    }
    float4 v = *src;
    float4 r;
    r.x = f2tff(v.x); r.y = f2tff(v.y); r.z = f2tff(v.z); r.w = f2tff(v.w);
    *dst = r;
}

// ---------------------------------------------------------------------------
// Kernel 1: fused QKV projection, tf32 mma, cp.async double-buffered (R6).
// Epilogue: Q natural, K d-permuted, V transposed+t-permuted (all rounded).
// ---------------------------------------------------------------------------
#define AST 20
#define BST 136
#define ASTG (128*AST)
#define BSTG (16*BST)

__global__ __launch_bounds__(128) void qkv_mma_kernel()
{
    __shared__ float As[2 * ASTG];
    __shared__ float Bs[2 * BSTG];

    const int z = blockIdx.z;
    const float* __restrict__ X = g_x32;
    const float* __restrict__ W = &g_w32[z][0];

    const int m0 = blockIdx.y * 128, n0 = blockIdx.x * 128;
    const int tid = threadIdx.x, lane = tid & 31, warp = tid >> 5;
    const int g = lane >> 2, tq = lane & 3;
    const int wm = (warp >> 1) * 64, wn = (warp & 1) * 64;

    const unsigned sA = (unsigned)__cvta_generic_to_shared(As);
    const unsigned sB = (unsigned)__cvta_generic_to_shared(Bs);

    const int ar = tid >> 2, ac4 = tid & 3;
    const int bk = tid >> 5, bc4 = tid & 31;

#define ISSUE(CH, ST) do {                                                   \
    const float* ga_ = X + (size_t)(m0 + ar) * DIN_ + (CH) * 16 + ac4 * 4;   \
    unsigned da_ = sA + (unsigned)(((ST) * ASTG + ar * AST + ac4 * 4) * 4);  \
    _Pragma("unroll")                                                        \
    for (int u_ = 0; u_ < 4; u_++)                                           \
        asm volatile("cp.async.cg.shared.global [%0], [%1], 16;"             \
            :: "r"(da_ + u_ * 32 * AST * 4), "l"(ga_ + (size_t)32 * u_ * DIN_)); \
    const float* gb_ = W + (size_t)((CH) * 16 + bk) * DINNER_ + n0 + bc4 * 4;\
    unsigned db_ = sB + (unsigned)(((ST) * BSTG + bk * BST + bc4 * 4) * 4);  \
    _Pragma("unroll")                                                        \
    for (int u_ = 0; u_ < 4; u_++)                                           \
        asm volatile("cp.async.cg.shared.global [%0], [%1], 16;"             \
            :: "r"(db_ + u_ * 4 * BST * 4), "l"(gb_ + (size_t)4 * u_ * DINNER_)); \
    asm volatile("cp.async.commit_group;" ::: "memory");                     \
} while (0)

    float acc[4][8][4];
    #pragma unroll
    for (int i = 0; i < 4; i++)
        #pragma unroll
        for (int j = 0; j < 8; j++)
            #pragma unroll
            for (int r = 0; r < 4; r++) acc[i][j][r] = 0.f;

    const unsigned* Au = (const unsigned*)As;
    const unsigned* Bu = (const unsigned*)Bs;

    ISSUE(0, 0);

    for (int ch = 0; ch < 64; ++ch) {
        const int st = ch & 1;
        if (ch < 63) {
            ISSUE(ch + 1, st ^ 1);
            asm volatile("cp.async.wait_group 1;" ::: "memory");
        } else {
            asm volatile("cp.async.wait_group 0;" ::: "memory");
        }
        __syncthreads();

        const unsigned* A0 = Au + st * ASTG;
        const unsigned* B0 = Bu + st * BSTG;
        #pragma unroll
        for (int ks = 0; ks < 2; ++ks) {
            unsigned a0[4], a1[4], a2[4], a3[4];
            #pragma unroll
            for (int mf = 0; mf < 4; mf++) {
                int base = (wm + mf * 16 + g) * AST + ks * 8 + tq;
                a0[mf] = A0[base];
                a2[mf] = A0[base + 4];
                a1[mf] = A0[base + 8 * AST];
                a3[mf] = A0[base + 8 * AST + 4];
            }
            unsigned b0[8], b1[8];
            #pragma unroll
            for (int nf = 0; nf < 8; nf++) {
                int cidx = wn + nf * 8 + g;
                b0[nf] = B0[(ks * 8 + tq) * BST + cidx];
                b1[nf] = B0[(ks * 8 + tq + 4) * BST + cidx];
            }
            #pragma unroll
            for (int mf = 0; mf < 4; mf++)
                #pragma unroll
                for (int nf = 0; nf < 8; nf++)
                    mma8(acc[mf][nf], a0[mf], a1[mf], a2[mf], a3[mf], b0[nf], b1[nf]);
        }
        __syncthreads();
    }

    // Epilogue
    #pragma unroll
    for (int mf = 0; mf < 4; mf++) {
        int row_a = m0 + wm + mf * 16 + g;
        int row_b = row_a + 8;
        int ba = row_a >> 11, ta = row_a & 2047;
        int bbq = row_b >> 11, tb = row_b & 2047;
        #pragma unroll
        for (int nf = 0; nf < 8; nf++) {
            int col = n0 + wn + nf * 8 + 2 * tq;
            int h = col >> 6, d = col & 63;
            float v0 = f2tff(acc[mf][nf][0]);
            float v1 = f2tff(acc[mf][nf][1]);
            float v2 = f2tff(acc[mf][nf][2]);
            float v3 = f2tff(acc[mf][nf][3]);
            if (z == 0) {
                *(float2*)(g_Q + ((size_t)((ba * H_ + h) * T_) + ta) * DH_ + d)
                    = make_float2(v0, v1);
                *(float2*)(g_Q + ((size_t)((bbq * H_ + h) * T_) + tb) * DH_ + d)
                    = make_float2(v2, v3);
            } else if (z == 1) {
                int pd = perm8(d);
                float* oa = g_K + ((size_t)((ba * H_ + h) * T_) + ta) * DH_;
                oa[pd] = v0; oa[pd + 2] = v1;
                float* ob = g_K + ((size_t)((bbq * H_ + h) * T_) + tb) * DH_;
                ob[pd] = v2; ob[pd + 2] = v3;
            } else {
                float* vt0 = g_V + ((size_t)((ba * H_ + h) * DH_) + d) * T_;
                float* vt1 = vt0 + T_;
                int pa = perm8(ta), pb = perm8(tb);
                vt0[pa] = v0; vt1[pa] = v1;
                vt0[pb] = v2; vt1[pb] = v3;
            }
        }
    }
#undef ISSUE
}

// ---------------------------------------------------------------------------
// Kernel 2: causal flash attention, tf32 mma, cp.async double-buffered K/V
// (R6 structure). Deltas vs R6: fully-masked warps skip the last diagonal
// tile (bit-identical), P fed as raw fp32 (HW tf32 truncation, no CVTs).
// ---------------------------------------------------------------------------
#define KST 72
#define VST 72
#define KSTG (64*KST)
#define VSTG (64*VST)
#define ATTN_SMEM ((2*KSTG + 2*VSTG)*4)   // 73728 bytes

__global__ __launch_bounds__(128) void attn_mma_kernel()
{
    extern __shared__ float dsm[];
    float* Ksm = dsm;
    float* Vsm = dsm + 2 * KSTG;

    const int qt = 15 - blockIdx.x;       // heavy tiles first
    const int bh = blockIdx.y;
    const int tid = threadIdx.x, warp = tid >> 5, lane = tid & 31;
    const int g = lane >> 2, tq = lane & 3;
    const int q0w = qt * 128 + warp * 32;

    const float* __restrict__ Qp = g_Q + (size_t)bh * T_ * DH_;
    const float* __restrict__ Kp = g_K + (size_t)bh * T_ * DH_;
    const float* __restrict__ Vp = g_V + (size_t)bh * T_ * DH_;

    const unsigned sK = (unsigned)__cvta_generic_to_shared(Ksm);
    const unsigned sV = (unsigned)__cvta_generic_to_shared(Vsm);

#define KV_ISSUE(KT, ST) do {                                                \
    const float* gk_ = Kp + (size_t)(KT) * 4096;                             \
    const float* gv_ = Vp + (KT) * 64;                                       \
    _Pragma("unroll")                                                        \
    for (int u_ = 0; u_ < 8; u_++) {                                         \
        int f4_ = tid + 128 * u_;                                            \
        int row_ = f4_ >> 4, c4_ = f4_ & 15;                                 \
        unsigned dk_ = sK + (unsigned)(((ST) * KSTG + row_ * KST + c4_ * 4) * 4); \
        asm volatile("cp.async.cg.shared.global [%0], [%1], 16;"             \
            :: "r"(dk_), "l"(gk_ + f4_ * 4));                                \
        unsigned dv_ = sV + (unsigned)(((ST) * VSTG + row_ * VST + c4_ * 4) * 4); \
        asm volatile("cp.async.cg.shared.global [%0], [%1], 16;"             \
            :: "r"(dv_), "l"(gv_ + (size_t)row_ * T_ + c4_ * 4));            \
    }                                                                        \
    asm volatile("cp.async.commit_group;" ::: "memory");                     \
} while (0)

    unsigned qf[2][8][4];
    #pragma unroll
    for (int m = 0; m < 2; m++) {
        const unsigned* qa = (const unsigned*)(Qp + (size_t)(q0w + 16 * m + g) * DH_);
        const unsigned* qb = qa + 8 * DH_;
        #pragma unroll
        for (int ks = 0; ks < 8; ks++) {
            qf[m][ks][0] = qa[ks * 8 + tq];
            qf[m][ks][1] = qb[ks * 8 + tq];
            qf[m][ks][2] = qa[ks * 8 + tq + 4];
            qf[m][ks][3] = qb[ks * 8 + tq + 4];
        }
    }

    float of[2][8][4];
    #pragma unroll
    for (int m = 0; m < 2; m++)
        #pragma unroll
        for (int d = 0; d < 8; d++)
            #pragma unroll
            for (int r = 0; r < 4; r++) of[m][d][r] = 0.f;
    float ls[2][2] = {{0.f, 0.f}, {0.f, 0.f}};

    const int grp = lane & ~3;
    const int sl0 = grp + (tq >> 1), sl1 = sl0 + 2;
    const bool od = (tq & 1);

    const unsigned* Ku = (const unsigned*)Ksm;
    const unsigned* Vu = (const unsigned*)Vsm;

    const int ktmax = 2 * qt + 1;
    KV_ISSUE(0, 0);

    for (int kt = 0; kt <= ktmax; ++kt) {
        const int st = kt & 1;
        __syncthreads();
        if (kt < ktmax) {
            KV_ISSUE(kt + 1, st ^ 1);
            asm volatile("cp.async.wait_group 1;" ::: "memory");
        } else {
            asm volatile("cp.async.wait_group 0;" ::: "memory");
        }
        __syncthreads();

        // Fully-masked warps skip the last diagonal tile (exp underflows to
        // exactly 0 for every element -> bit-identical).
        if (kt == ktmax && warp < 2) continue;

        const unsigned* K0 = Ku + st * KSTG;
        const unsigned* V0 = Vu + st * VSTG;

        // ---- S = Q K^T ----
        float c[2][8][4];
        #pragma unroll
        for (int m = 0; m < 2; m++)
            #pragma unroll
            for (int nf = 0; nf < 8; nf++)
                #pragma unroll
                for (int r = 0; r < 4; r++) c[m][nf][r] = 0.f;

        #pragma unroll
        for (int ks = 0; ks < 8; ks++) {
            uint2 kb[8];
            #pragma unroll
            for (int nf = 0; nf < 8; nf++)
                kb[nf] = *(const uint2*)&K0[(nf * 8 + g) * KST + ks * 8 + 2 * tq];
            #pragma unroll
            for (int m = 0; m < 2; m++)
                #pragma unroll
                for (int nf = 0; nf < 8; nf++)
                    mma8(c[m][nf], qf[m][ks][0], qf[m][ks][1], qf[m][ks][2], qf[m][ks][3],
                         kb[nf].x, kb[nf].y);
        }

        // ---- causal mask ----
        if (kt >= 2 * qt) {
            const int base = kt * 64;
            #pragma unroll
            for (int m = 0; m < 2; m++) {
                int r0 = q0w + 16 * m + g, r1 = r0 + 8;
                #pragma unroll
                for (int nf = 0; nf < 8; nf++) {
                    int col = base + nf * 8 + 2 * tq;
                    if (col     > r0) c[m][nf][0] = -1e30f;
                    if (col + 1 > r0) c[m][nf][1] = -1e30f;
                    if (col     > r1) c[m][nf][2] = -1e30f;
                    if (col + 1 > r1) c[m][nf][3] = -1e30f;
                }
            }
        }

        // ---- p = exp(s/32) ----
        #pragma unroll
        for (int m = 0; m < 2; m++)
            #pragma unroll
            for (int nf = 0; nf < 8; nf++) {
                c[m][nf][0] = __expf(c[m][nf][0] * 0.03125f);
                c[m][nf][1] = __expf(c[m][nf][1] * 0.03125f);
                c[m][nf][2] = __expf(c[m][nf][2] * 0.03125f);
                c[m][nf][3] = __expf(c[m][nf][3] * 0.03125f);
                ls[m][0] += c[m][nf][0] + c[m][nf][1];
                ls[m][1] += c[m][nf][2] + c[m][nf][3];
            }

        // ---- O += P V : P as raw fp32 (HW truncates to tf32) ----
        #pragma unroll
        for (int kk = 0; kk < 8; kk++) {
            unsigned A[2][4];
            #pragma unroll
            for (int m = 0; m < 2; m++) {
                float e0 = __shfl_sync(FULLM, c[m][kk][0], sl0);
                float o0 = __shfl_sync(FULLM, c[m][kk][1], sl0);
                float e1 = __shfl_sync(FULLM, c[m][kk][0], sl1);
                float o1 = __shfl_sync(FULLM, c[m][kk][1], sl1);
                float e2 = __shfl_sync(FULLM, c[m][kk][2], sl0);
                float o2 = __shfl_sync(FULLM, c[m][kk][3], sl0);
                float e3 = __shfl_sync(FULLM, c[m][kk][2], sl1);
                float o3 = __shfl_sync(FULLM, c[m][kk][3], sl1);
                A[m][0] = __float_as_uint(od ? o0 : e0);
                A[m][2] = __float_as_uint(od ? o1 : e1);
                A[m][1] = __float_as_uint(od ? o2 : e2);
                A[m][3] = __float_as_uint(od ? o3 : e3);
            }
            #pragma unroll
            for (int df = 0; df < 8; df++) {
                uint2 vb = *(const uint2*)&V0[(df * 8 + g) * VST + kk * 8 + 2 * tq];
                mma8(of[0][df], A[0][0], A[0][1], A[0][2], A[0][3], vb.x, vb.y);
                mma8(of[1][df], A[1][0], A[1][1], A[1][2], A[1][3], vb.x, vb.y);
            }
        }
    }
#undef KV_ISSUE

    #pragma unroll
    for (int m = 0; m < 2; m++)
        #pragma unroll
        for (int r = 0; r < 2; r++) {
            ls[m][r] += __shfl_xor_sync(FULLM, ls[m][r], 1);
            ls[m][r] += __shfl_xor_sync(FULLM, ls[m][r], 2);
        }

    const int bb = bh >> 4, hh = bh & 15;
    #pragma unroll
    for (int m = 0; m < 2; m++) {
        float i0 = 1.f / ls[m][0], i1 = 1.f / ls[m][1];
        int rowa = q0w + 16 * m + g, rowb = rowa + 8;
        float* oa = g_attn + (size_t)(bb * T_ + rowa) * DINNER_ + hh * 64;
        float* ob = g_attn + (size_t)(bb * T_ + rowb) * DINNER_ + hh * 64;
        #pragma unroll
        for (int df = 0; df < 8; df++) {
            *(float2*)(oa + df * 8 + 2 * tq)
                = make_float2(f2tff(of[m][df][0] * i0), f2tff(of[m][df][1] * i0));
            *(float2*)(ob + df * 8 + 2 * tq)
                = make_float2(f2tff(of[m][df][2] * i1), f2tff(of[m][df][3] * i1));
        }
    }
}

// ---------------------------------------------------------------------------
// Kernel 3: out projection via tf32 mma (R6 version: smem-staged, 20 µs).
// CTA: 32 rows, 128 thr, 128 CTAs, cp.async double-buffer, KC=32.
// ---------------------------------------------------------------------------
#define OAST 36
#define OBST 72
#define OASTG (32*OAST)
#define OBSTG (32*OBST)

__global__ __launch_bounds__(128) void out_mma_kernel(
    const float* __restrict__ bo, float* __restrict__ out)
{
    __shared__ float As3[2 * OASTG];
    __shared__ float Bs3[2 * OBSTG];

    const int m0 = blockIdx.x * 32;
    const int tid = threadIdx.x, lane = tid & 31, warp = tid >> 5;
    const int g = lane >> 2, tq = lane & 3;
    const int wm = (warp >> 1) * 16, wn = (warp & 1) * 32;

    const unsigned sA = (unsigned)__cvta_generic_to_shared(As3);
    const unsigned sB = (unsigned)__cvta_generic_to_shared(Bs3);

    const int ar = tid >> 2, ac4 = tid & 3;

#define OISSUE(CH, ST) do {                                                  \
    const float* ga_ = g_attn + (size_t)(m0 + ar) * DINNER_ + (CH) * 32 + ac4 * 4; \
    unsigned da_ = sA + (unsigned)(((ST) * OASTG + ar * OAST + ac4 * 4) * 4);\
    asm volatile("cp.async.cg.shared.global [%0], [%1], 16;"                 \
        :: "r"(da_), "l"(ga_));                                              \
    asm volatile("cp.async.cg.shared.global [%0], [%1], 16;"                 \
        :: "r"(da_ + 16 * 4), "l"(ga_ + 16));                                \
    _Pragma("unroll")                                                        \
    for (int u_ = 0; u_ < 4; u_++) {                                         \
        int i_ = tid + 128 * u_;                                             \
        int kr_ = i_ >> 4, c4_ = i_ & 15;                                    \
        unsigned db_ = sB + (unsigned)(((ST) * OBSTG + kr_ * OBST + c4_ * 4) * 4); \
        asm volatile("cp.async.cg.shared.global [%0], [%1], 16;"             \
            :: "r"(db_), "l"(g_wo32 + (size_t)((CH) * 32 + kr_) * DOUT_ + c4_ * 4)); \
    }                                                                        \
    asm volatile("cp.async.commit_group;" ::: "memory");                     \
} while (0)

    float acc[4][4];
    #pragma unroll
    for (int j = 0; j < 4; j++)
        #pragma unroll
        for (int r = 0; r < 4; r++) acc[j][r] = 0.f;

    const unsigned* Au = (const unsigned*)As3;
    const unsigned* Bu = (const unsigned*)Bs3;

    OISSUE(0, 0);

    for (int ch = 0; ch < 32; ++ch) {
        const int st = ch & 1;
        if (ch < 31) {
            OISSUE(ch + 1, st ^ 1);
            asm volatile("cp.async.wait_group 1;" ::: "memory");
        } else {
            asm volatile("cp.async.wait_group 0;" ::: "memory");
        }
        __syncthreads();

        const unsigned* A0 = Au + st * OASTG;
        const unsigned* B0 = Bu + st * OBSTG;
        #pragma unroll
        for (int ks = 0; ks < 4; ++ks) {
            int basea = (wm + g) * OAST + ks * 8 + tq;
            unsigned a0 = A0[basea];
            unsigned a2 = A0[basea + 4];
            unsigned a1 = A0[basea + 8 * OAST];
            unsigned a3 = A0[basea + 8 * OAST + 4];
            #pragma unroll
            for (int nf = 0; nf < 4; nf++) {
                unsigned b0 = B0[(ks * 8 + tq) * OBST + wn + nf * 8 + g];
                unsigned b1 = B0[(ks * 8 + tq + 4) * OBST + wn + nf * 8 + g];
                mma8(acc[nf], a0, a1, a2, a3, b0, b1);
            }
        }
        __syncthreads();
    }

    const int row_a = m0 + wm + g, row_b = row_a + 8;
    #pragma unroll
    for (int nf = 0; nf < 4; nf++) {
        int col = wn + nf * 8 + 2 * tq;
        float2 bias = *(const float2*)(bo + col);
        *(float2*)(out + (size_t)row_a * DOUT_ + col)
            = make_float2(acc[nf][0] + bias.x, acc[nf][1] + bias.y);
        *(float2*)(out + (size_t)row_b * DOUT_ + col)
            = make_float2(acc[nf][2] + bias.x, acc[nf][3] + bias.y);
    }
#undef OISSUE
}

// ---------------------------------------------------------------------------
extern "C" void kernel_launch(void* const* d_in, const int* in_sizes, int n_in,
                              void* d_out, int out_size)
{
    const float* x  = (const float*)d_in[0];
    const float* Wq = (const float*)d_in[1];
    const float* Wk = (const float*)d_in[2];
    const float* Wv = (const float*)d_in[3];
    const float* Wo = (const float*)d_in[4];
    const float* bo = (const float*)d_in[5];
    float* out = (float*)d_out;
    (void)in_sizes; (void)n_in; (void)out_size;

    cudaFuncSetAttribute(attn_mma_kernel,
                         cudaFuncAttributeMaxDynamicSharedMemorySize, ATTN_SMEM);

    tf32_round_all<<<(TOTF4 + 255) / 256, 256>>>(
        (const float4*)x, (const float4*)Wq, (const float4*)Wk,
        (const float4*)Wv, (const float4*)Wo);

    qkv_mma_kernel<<<dim3(8, 32, 3), 128>>>();
    attn_mma_kernel<<<dim3(16, 32), 128, ATTN_SMEM>>>();
    out_mma_kernel<<<BT_ / 32, 128>>>(bo, out);
}

// round 10
// speedup vs baseline: 2.3300x; 1.8311x over previous
#include <cuda_runtime.h>

#define B_ 2
#define T_ 2048
#define H_ 16
#define DH_ 64
#define DIN_ 1024
#define DINNER_ 1024
#define DOUT_ 64
#define BT_ 4096

#define FULLM 0xffffffffu

// All fp16 operands stored as packed half2 in unsigned words.
__device__ unsigned g_x16[BT_*DIN_/2];        // [row][k2]      half2(k, k+1)
__device__ unsigned g_w16[3][DIN_/2*DINNER_]; // [k2][n]        half2(k, k+1)
__device__ unsigned g_wo16[DINNER_/2*DOUT_];  // [k2][n]        half2(k, k+1)
__device__ unsigned g_Q16[B_*H_*T_*DH_/2];    // [bh][t][d2]    half2(d, d+1)
__device__ unsigned g_K16[B_*H_*T_*DH_/2];    // [bh][d2][t]    half2(d, d+1)
__device__ unsigned g_V16[B_*H_*T_*DH_/2];    // [bh][t2][d]    half2(t, t+1)
__device__ unsigned g_attn16[BT_*DINNER_/2];  // [row][d2]      half2(d, d+1)

__device__ __forceinline__ unsigned packh2(float hi, float lo) {
    unsigned u;
    asm("cvt.rn.f16x2.f32 %0, %1, %2;" : "=r"(u) : "f"(hi), "f"(lo));
    return u;
}
__device__ __forceinline__ void mma16(float c[4],
    unsigned a0, unsigned a1, unsigned a2, unsigned a3,
    unsigned b0, unsigned b1)
{
    asm volatile("mma.sync.aligned.m16n8k16.row.col.f32.f16.f16.f32 "
        "{%0,%1,%2,%3}, {%4,%5,%6,%7}, {%8,%9}, {%0,%1,%2,%3};"
        : "+f"(c[0]), "+f"(c[1]), "+f"(c[2]), "+f"(c[3])
        : "r"(a0), "r"(a1), "r"(a2), "r"(a3), "r"(b0), "r"(b1));
}

// ---------------------------------------------------------------------------
// Kernel 0: pack all GEMM inputs to fp16 half2 in ONE launch.
// ---------------------------------------------------------------------------
#define XU  (BT_*DIN_/4)        // 1048576
#define WU  (DIN_/2*DINNER_)    // 524288 (2^19)
#define WOU (DINNER_/2*DOUT_)   // 32768
#define PRETOT (XU + 3*WU + WOU)

__global__ __launch_bounds__(256) void pack16_all(
    const float4* __restrict__ x, const float* __restrict__ wq,
    const float* __restrict__ wk, const float* __restrict__ wv,
    const float* __restrict__ wo)
{
    int i = blockIdx.x * 256 + threadIdx.x;
    if (i >= PRETOT) return;
    if (i < XU) {
        float4 v = x[i];
        g_x16[2 * i]     = packh2(v.y, v.x);
        g_x16[2 * i + 1] = packh2(v.w, v.z);
    } else {
        int j = i - XU;
        if (j < 3 * WU) {
            int w = j >> 19;
            int o = j & (WU - 1);
            int k2 = o >> 10, n = o & 1023;
            const float* W = (w == 0) ? wq : (w == 1) ? wk : wv;
            g_w16[w][o] = packh2(W[(2 * k2 + 1) * DINNER_ + n],
                                 W[(2 * k2) * DINNER_ + n]);
        } else {
            int o = j - 3 * WU;
            int k2 = o >> 6, n = o & 63;
            g_wo16[o] = packh2(wo[(2 * k2 + 1) * DOUT_ + n],
                               wo[(2 * k2) * DOUT_ + n]);
        }
    }
}

// ---------------------------------------------------------------------------
// Kernel 1: fused QKV projection, fp16 m16n8k16 mma, cp.async double-buffer.
// Epilogue: Q [t][d2], K [d2][t], V [t2][d] (t-paired via lane^4 shuffles).
// ---------------------------------------------------------------------------
#define AST 20
#define BST 136
#define ASTG (128*AST)
#define BSTG (16*BST)

__global__ __launch_bounds__(128) void qkv_mma_kernel()
{
    __shared__ unsigned As[2 * ASTG];
    __shared__ unsigned Bs[2 * BSTG];

    const int z = blockIdx.z;
    const unsigned* __restrict__ X = g_x16;
    const unsigned* __restrict__ W = g_w16[z];

    const int m0 = blockIdx.y * 128, n0 = blockIdx.x * 128;
    const int tid = threadIdx.x, lane = tid & 31, warp = tid >> 5;
    const int g = lane >> 2, tq = lane & 3;
    const int wm = (warp >> 1) * 64, wn = (warp & 1) * 64;

    const unsigned sA = (unsigned)__cvta_generic_to_shared(As);
    const unsigned sB = (unsigned)__cvta_generic_to_shared(Bs);

    const int ar = tid >> 2, ac4 = tid & 3;
    const int bk = tid >> 5, bc4 = tid & 31;

#define ISSUE(CH, ST) do {                                                    \
    _Pragma("unroll")                                                         \
    for (int u_ = 0; u_ < 4; u_++) {                                          \
        const unsigned* ga_ = X + (size_t)(m0 + ar + 32 * u_) * (DIN_/2)      \
                              + (CH) * 16 + ac4 * 4;                          \
        unsigned da_ = sA + (unsigned)(((ST) * ASTG + (ar + 32 * u_) * AST    \
                              + ac4 * 4) * 4);                                \
        asm volatile("cp.async.cg.shared.global [%0], [%1], 16;"              \
            :: "r"(da_), "l"(ga_));                                           \
    }                                                                         \
    _Pragma("unroll")                                                         \
    for (int u_ = 0; u_ < 4; u_++) {                                          \
        const unsigned* gb_ = W + (size_t)((CH) * 16 + bk + 4 * u_) * DINNER_ \
                              + n0 + bc4 * 4;                                 \
        unsigned db_ = sB + (unsigned)(((ST) * BSTG + (bk + 4 * u_) * BST     \
                              + bc4 * 4) * 4);                                \
        asm volatile("cp.async.cg.shared.global [%0], [%1], 16;"              \
            :: "r"(db_), "l"(gb_));                                           \
    }                                                                         \
    asm volatile("cp.async.commit_group;" ::: "memory");                      \
} while (0)

    float acc[4][8][4];
    #pragma unroll
    for (int i = 0; i < 4; i++)
        #pragma unroll
        for (int j = 0; j < 8; j++)
            #pragma unroll
            for (int r = 0; r < 4; r++) acc[i][j][r] = 0.f;

    ISSUE(0, 0);

    for (int ch = 0; ch < 32; ++ch) {
        const int st = ch & 1;
        if (ch < 31) {
            ISSUE(ch + 1, st ^ 1);
            asm volatile("cp.async.wait_group 1;" ::: "memory");
        } else {
            asm volatile("cp.async.wait_group 0;" ::: "memory");
        }
        __syncthreads();

        const unsigned* A0 = As + st * ASTG;
        const unsigned* B0 = Bs + st * BSTG;
        #pragma unroll
        for (int ks = 0; ks < 2; ++ks) {
            unsigned a0[4], a1[4], a2[4], a3[4];
            #pragma unroll
            for (int mf = 0; mf < 4; mf++) {
                int r0 = (wm + mf * 16 + g) * AST + ks * 8 + tq;
                int r1 = r0 + 8 * AST;
                a0[mf] = A0[r0];
                a2[mf] = A0[r0 + 4];
                a1[mf] = A0[r1];
                a3[mf] = A0[r1 + 4];
            }
            unsigned b0[8], b1[8];
            #pragma unroll
            for (int nf = 0; nf < 8; nf++) {
                int cidx = wn + nf * 8 + g;
                b0[nf] = B0[(ks * 8 + tq) * BST + cidx];
                b1[nf] = B0[(ks * 8 + tq + 4) * BST + cidx];
            }
            #pragma unroll
            for (int mf = 0; mf < 4; mf++)
                #pragma unroll
                for (int nf = 0; nf < 8; nf++)
                    mma16(acc[mf][nf], a0[mf], a1[mf], a2[mf], a3[mf],
                          b0[nf], b1[nf]);
        }
        __syncthreads();
    }

    // Epilogue
    const int bb = m0 >> 11;
    #pragma unroll
    for (int mf = 0; mf < 4; mf++) {
        int row_a = m0 + wm + mf * 16 + g;
        int row_b = row_a + 8;
        int ta = row_a & 2047, tb = row_b & 2047;
        #pragma unroll
        for (int nf = 0; nf < 8; nf++) {
            int col = n0 + wn + nf * 8 + 2 * tq;
            int h = col >> 6, d = col & 63;     // d even
            float v0 = acc[mf][nf][0], v1 = acc[mf][nf][1];
            float v2 = acc[mf][nf][2], v3 = acc[mf][nf][3];
            if (z == 0) {
                g_Q16[((size_t)((bb * H_ + h) * T_) + ta) * 32 + (d >> 1)]
                    = packh2(v1, v0);
                g_Q16[((size_t)((bb * H_ + h) * T_) + tb) * 32 + (d >> 1)]
                    = packh2(v3, v2);
            } else if (z == 1) {
                g_K16[((size_t)((bb * H_ + h) * 32) + (d >> 1)) * T_ + ta]
                    = packh2(v1, v0);
                g_K16[((size_t)((bb * H_ + h) * 32) + (d >> 1)) * T_ + tb]
                    = packh2(v3, v2);
            } else {
                // V^T packed along t. Rows t, t+1 live at fragment rows
                // g, g^1 -> partner lane is lane^4 (lane = 4g + tq).
                float s0 = __shfl_xor_sync(FULLM, v0, 4);
                float s1 = __shfl_xor_sync(FULLM, v1, 4);
                float s2 = __shfl_xor_sync(FULLM, v2, 4);
                float s3 = __shfl_xor_sync(FULLM, v3, 4);
                bool odd = (g & 1);
                unsigned ua = odd ? packh2(v1, s1) : packh2(s0, v0);
                unsigned ub = odd ? packh2(v3, s3) : packh2(s2, v2);
                int dcol = d + (g & 1);
                g_V16[((size_t)((bb * H_ + h) * 1024) + (ta >> 1)) * 64 + dcol] = ua;
                g_V16[((size_t)((bb * H_ + h) * 1024) + (tb >> 1)) * 64 + dcol] = ub;
            }
        }
    }
#undef ISSUE
}

// ---------------------------------------------------------------------------
// Kernel 2: causal flash attention, fp16 m16n8k16 mma, cp.async double-buffer.
// P converts C-frag -> A-frag with pure register packs (no shuffles).
// Masked warps skip last diag tile. Ks [d2][key] / Vs [t2][d], stride 72.
// ---------------------------------------------------------------------------
#define KST 72
#define VST 72
#define KSTG (32*KST)
#define VSTG (32*VST)

__global__ __launch_bounds__(128) void attn_mma_kernel()
{
    __shared__ unsigned Ks[2 * KSTG];
    __shared__ unsigned Vs[2 * VSTG];

    const int qt = 15 - blockIdx.x;       // heavy tiles first
    const int bh = blockIdx.y;
    const int tid = threadIdx.x, warp = tid >> 5, lane = tid & 31;
    const int g = lane >> 2, tq = lane & 3;
    const int q0w = qt * 128 + warp * 32;

    const unsigned* __restrict__ Qp = g_Q16 + (size_t)bh * T_ * 32;
    const unsigned* __restrict__ Kb = g_K16 + (size_t)bh * 32 * T_;
    const unsigned* __restrict__ Vb = g_V16 + (size_t)bh * 1024 * 64;

    const unsigned sK = (unsigned)__cvta_generic_to_shared(Ks);
    const unsigned sV = (unsigned)__cvta_generic_to_shared(Vs);

#define KV_ISSUE(KT, ST) do {                                                 \
    _Pragma("unroll")                                                         \
    for (int u_ = 0; u_ < 4; u_++) {                                          \
        int row_ = (tid >> 4) + 8 * u_;                                       \
        int c4_ = tid & 15;                                                   \
        unsigned dk_ = sK + (unsigned)(((ST) * KSTG + row_ * KST + c4_ * 4) * 4); \
        asm volatile("cp.async.cg.shared.global [%0], [%1], 16;"              \
            :: "r"(dk_), "l"(Kb + (size_t)row_ * T_ + (KT) * 64 + c4_ * 4));  \
        unsigned dv_ = sV + (unsigned)(((ST) * VSTG + row_ * VST + c4_ * 4) * 4); \
        asm volatile("cp.async.cg.shared.global [%0], [%1], 16;"              \
            :: "r"(dv_), "l"(Vb + (size_t)((KT) * 32 + row_) * 64 + c4_ * 4)); \
    }                                                                         \
    asm volatile("cp.async.commit_group;" ::: "memory");                      \
} while (0)

    // Q fragments (raw fp16 half2 bits; 1/32 scale folded into expf)
    unsigned qf[2][4][4];
    #pragma unroll
    for (int m = 0; m < 2; m++) {
        const unsigned* qa = Qp + (size_t)(q0w + 16 * m + g) * 32;
        const unsigned* qb = qa + 8 * 32;
        #pragma unroll
        for (int ks = 0; ks < 4; ks++) {
            qf[m][ks][0] = qa[ks * 8 + tq];
            qf[m][ks][1] = qb[ks * 8 + tq];
            qf[m][ks][2] = qa[ks * 8 + tq + 4];
            qf[m][ks][3] = qb[ks * 8 + tq + 4];
        }
    }

    float of[2][8][4];
    #pragma unroll
    for (int m = 0; m < 2; m++)
        #pragma unroll
        for (int d = 0; d < 8; d++)
            #pragma unroll
            for (int r = 0; r < 4; r++) of[m][d][r] = 0.f;
    float ls[2][2] = {{0.f, 0.f}, {0.f, 0.f}};

    const int ktmax = 2 * qt + 1;
    KV_ISSUE(0, 0);

    for (int kt = 0; kt <= ktmax; ++kt) {
        const int st = kt & 1;
        __syncthreads();
        if (kt < ktmax) {
            KV_ISSUE(kt + 1, st ^ 1);
            asm volatile("cp.async.wait_group 1;" ::: "memory");
        } else {
            asm volatile("cp.async.wait_group 0;" ::: "memory");
        }
        __syncthreads();

        // Fully-masked warps skip the last diagonal tile (bit-identical).
        if (kt == ktmax && warp < 2) continue;

        const unsigned* K0 = Ks + st * KSTG;
        const unsigned* V0 = Vs + st * VSTG;

        // ---- S = Q K^T ----
        float c[2][8][4];
        #pragma unroll
        for (int m = 0; m < 2; m++)
            #pragma unroll
            for (int nf = 0; nf < 8; nf++)
                #pragma unroll
                for (int r = 0; r < 4; r++) c[m][nf][r] = 0.f;

        #pragma unroll
        for (int ks = 0; ks < 4; ks++) {
            unsigned b0[8], b1[8];
            #pragma unroll
            for (int nf = 0; nf < 8; nf++) {
                int cidx = nf * 8 + g;
                b0[nf] = K0[(ks * 8 + tq) * KST + cidx];
                b1[nf] = K0[(ks * 8 + tq + 4) * KST + cidx];
            }
            #pragma unroll
            for (int m = 0; m < 2; m++)
                #pragma unroll
                for (int nf = 0; nf < 8; nf++)
                    mma16(c[m][nf], qf[m][ks][0], qf[m][ks][1],
                          qf[m][ks][2], qf[m][ks][3], b0[nf], b1[nf]);
        }

        // ---- causal mask ----
        if (kt >= 2 * qt) {
            const int base = kt * 64;
            #pragma unroll
            for (int m = 0; m < 2; m++) {
                int r0 = q0w + 16 * m + g, r1 = r0 + 8;
                #pragma unroll
                for (int nf = 0; nf < 8; nf++) {
                    int col = base + nf * 8 + 2 * tq;
                    if (col     > r0) c[m][nf][0] = -1e30f;
                    if (col + 1 > r0) c[m][nf][1] = -1e30f;
                    if (col     > r1) c[m][nf][2] = -1e30f;
                    if (col + 1 > r1) c[m][nf][3] = -1e30f;
                }
            }
        }

        // ---- p = exp(s/32) ----
        #pragma unroll
        for (int m = 0; m < 2; m++)
            #pragma unroll
            for (int nf = 0; nf < 8; nf++) {
                c[m][nf][0] = __expf(c[m][nf][0] * 0.03125f);
                c[m][nf][1] = __expf(c[m][nf][1] * 0.03125f);
                c[m][nf][2] = __expf(c[m][nf][2] * 0.03125f);
                c[m][nf][3] = __expf(c[m][nf][3] * 0.03125f);
                ls[m][0] += c[m][nf][0] + c[m][nf][1];
                ls[m][1] += c[m][nf][2] + c[m][nf][3];
            }

        // ---- O += P V : pack P directly into A-fragments (no shuffles) ----
        #pragma unroll
        for (int j = 0; j < 4; j++) {
            unsigned A[2][4];
            #pragma unroll
            for (int m = 0; m < 2; m++) {
                A[m][0] = packh2(c[m][2 * j][1],     c[m][2 * j][0]);
                A[m][1] = packh2(c[m][2 * j][3],     c[m][2 * j][2]);
                A[m][2] = packh2(c[m][2 * j + 1][1], c[m][2 * j + 1][0]);
                A[m][3] = packh2(c[m][2 * j + 1][3], c[m][2 * j + 1][2]);
            }
            #pragma unroll
            for (int df = 0; df < 8; df++) {
                int cidx = df * 8 + g;
                unsigned vb0 = V0[(j * 8 + tq) * VST + cidx];
                unsigned vb1 = V0[(j * 8 + tq + 4) * VST + cidx];
                mma16(of[0][df], A[0][0], A[0][1], A[0][2], A[0][3], vb0, vb1);
                mma16(of[1][df], A[1][0], A[1][1], A[1][2], A[1][3], vb0, vb1);
            }
        }
    }
#undef KV_ISSUE

    #pragma unroll
    for (int m = 0; m < 2; m++)
        #pragma unroll
        for (int r = 0; r < 2; r++) {
            ls[m][r] += __shfl_xor_sync(FULLM, ls[m][r], 1);
            ls[m][r] += __shfl_xor_sync(FULLM, ls[m][r], 2);
        }

    // epilogue: fp16-pack g_attn (consumed by out-proj mma)
    const int bb = bh >> 4, hh = bh & 15;
    #pragma unroll
    for (int m = 0; m < 2; m++) {
        float i0 = 1.f / ls[m][0], i1 = 1.f / ls[m][1];
        int rowa = q0w + 16 * m + g, rowb = rowa + 8;
        unsigned* oa = g_attn16 + (size_t)(bb * T_ + rowa) * 512 + hh * 32;
        unsigned* ob = g_attn16 + (size_t)(bb * T_ + rowb) * 512 + hh * 32;
        #pragma unroll
        for (int df = 0; df < 8; df++) {
            oa[df * 4 + tq] = packh2(of[m][df][1] * i0, of[m][df][0] * i0);
            ob[df * 4 + tq] = packh2(of[m][df][3] * i1, of[m][df][2] * i1);
        }
    }
}

// ---------------------------------------------------------------------------
// Kernel 3: out projection via fp16 mma. out[4096,64] = attn @ Wo + bo.
// ---------------------------------------------------------------------------
#define OAST 20
#define OBST 72
#define OASTG (32*OAST)
#define OBSTG (16*OBST)

__global__ __launch_bounds__(128) void out_mma_kernel(
    const float* __restrict__ bo, float* __restrict__ out)
{
    __shared__ unsigned As3[2 * OASTG];
    __shared__ unsigned Bs3[2 * OBSTG];

    const int m0 = blockIdx.x * 32;
    const int tid = threadIdx.x, lane = tid & 31, warp = tid >> 5;
    const int g = lane >> 2, tq = lane & 3;
    const int wm = (warp >> 1) * 16, wn = (warp & 1) * 32;

    const unsigned sA = (unsigned)__cvta_generic_to_shared(As3);
    const unsigned sB = (unsigned)__cvta_generic_to_shared(Bs3);

#define OISSUE(CH, ST) do {                                                   \
    {                                                                         \
        int row_ = tid >> 2, c4_ = tid & 3;                                   \
        unsigned da_ = sA + (unsigned)(((ST) * OASTG + row_ * OAST + c4_ * 4) * 4); \
        asm volatile("cp.async.cg.shared.global [%0], [%1], 16;"              \
            :: "r"(da_), "l"(g_attn16 + (size_t)(m0 + row_) * 512             \
                             + (CH) * 16 + c4_ * 4));                         \
    }                                                                         \
    _Pragma("unroll")                                                         \
    for (int u_ = 0; u_ < 2; u_++) {                                          \
        int k2r_ = (tid >> 4) + 8 * u_;                                       \
        int c4_ = tid & 15;                                                   \
        unsigned db_ = sB + (unsigned)(((ST) * OBSTG + k2r_ * OBST + c4_ * 4) * 4); \
        asm volatile("cp.async.cg.shared.global [%0], [%1], 16;"              \
            :: "r"(db_), "l"(g_wo16 + (size_t)((CH) * 16 + k2r_) * 64 + c4_ * 4)); \
    }                                                                         \
    asm volatile("cp.async.commit_group;" ::: "memory");                      \
} while (0)

    float acc[4][4];
    #pragma unroll
    for (int j = 0; j < 4; j++)
        #pragma unroll
        for (int r = 0; r < 4; r++) acc[j][r] = 0.f;

    OISSUE(0, 0);

    for (int ch = 0; ch < 32; ++ch) {
        const int st = ch & 1;
        if (ch < 31) {
            OISSUE(ch + 1, st ^ 1);
            asm volatile("cp.async.wait_group 1;" ::: "memory");
        } else {
            asm volatile("cp.async.wait_group 0;" ::: "memory");
        }
        __syncthreads();

        const unsigned* A0 = As3 + st * OASTG;
        const unsigned* B0 = Bs3 + st * OBSTG;
        #pragma unroll
        for (int ks = 0; ks < 2; ++ks) {
            int r0 = (wm + g) * OAST + ks * 8 + tq;
            int r1 = r0 + 8 * OAST;
            unsigned a0 = A0[r0];
            unsigned a2 = A0[r0 + 4];
            unsigned a1 = A0[r1];
            unsigned a3 = A0[r1 + 4];
            #pragma unroll
            for (int nf = 0; nf < 4; nf++) {
                int cidx = wn + nf * 8 + g;
                unsigned b0 = B0[(ks * 8 + tq) * OBST + cidx];
                unsigned b1 = B0[(ks * 8 + tq + 4) * OBST + cidx];
                mma16(acc[nf], a0, a1, a2, a3, b0, b1);
            }
        }
        __syncthreads();
    }

    const int row_a = m0 + wm + g, row_b = row_a + 8;
    #pragma unroll
    for (int nf = 0; nf < 4; nf++) {
        int col = wn + nf * 8 + 2 * tq;
        float2 bias = *(const float2*)(bo + col);
        *(float2*)(out + (size_t)row_a * DOUT_ + col)
            = make_float2(acc[nf][0] + bias.x, acc[nf][1] + bias.y);
        *(float2*)(out + (size_t)row_b * DOUT_ + col)
            = make_float2(acc[nf][2] + bias.x, acc[nf][3] + bias.y);
    }
#undef OISSUE
}

// ---------------------------------------------------------------------------
extern "C" void kernel_launch(void* const* d_in, const int* in_sizes, int n_in,
                              void* d_out, int out_size)
{
    const float* x  = (const float*)d_in[0];
    const float* Wq = (const float*)d_in[1];
    const float* Wk = (const float*)d_in[2];
    const float* Wv = (const float*)d_in[3];
    const float* Wo = (const float*)d_in[4];
    const float* bo = (const float*)d_in[5];
    float* out = (float*)d_out;
    (void)in_sizes; (void)n_in; (void)out_size;

    pack16_all<<<(PRETOT + 255) / 256, 256>>>(
        (const float4*)x, Wq, Wk, Wv, Wo);

    qkv_mma_kernel<<<dim3(8, 32, 3), 128>>>();
    attn_mma_kernel<<<dim3(16, 32), 128>>>();
    out_mma_kernel<<<BT_ / 32, 128>>>(bo, out);
}